// round 4
// baseline (speedup 1.0000x reference)
#include <cuda_runtime.h>

// ---------------------------------------------------------------------------
// CSNet14: 14 tiny linear layers with encoder/decoder skip connections and a
// 2-class softmax, batch 2,000,000 rows of 12 features.
//
// Strategy: FMA-pipe-bound problem. Each thread processes TWO rows packed as
// f32x2 in 64-bit registers; all math uses PTX fma.rn.f32x2 (SASS FFMA2, 2x
// fp32 FMA throughput). Weights/biases live in shared memory pre-duplicated
// as (w,w) 64-bit pairs so one broadcast LDS.64 feeds FFMA2 directly.
// ---------------------------------------------------------------------------

typedef unsigned long long u64;

#define NL 14

__host__ __device__ constexpr int DINf(int l) {
    const int d[NL] = {12, 12, 11, 10, 9, 8, 7, 6, 7, 8, 9, 10, 11, 12};
    return d[l];
}
__host__ __device__ constexpr int DOUTf(int l) {
    const int d[NL] = {12, 11, 10, 9, 8, 7, 6, 7, 8, 9, 10, 11, 12, 2};
    return d[l];
}
__host__ __device__ constexpr int WOFF(int l) {
    int s = 0;
    for (int i = 0; i < l; i++) s += DINf(i) * DOUTf(i);
    return s;
}
__host__ __device__ constexpr int BOFF(int l) {
    int s = WOFF(NL);
    for (int i = 0; i < l; i++) s += DOUTf(i);
    return s;
}
// total shared u64 slots = all weights + all biases
#define SH_SIZE (BOFF(NL))   // 1172 + 122 = 1294

// ---- packed f32x2 primitives -------------------------------------------------

__device__ __forceinline__ u64 f2fma(u64 a, u64 b, u64 c) {
    u64 d;
    asm("fma.rn.f32x2 %0, %1, %2, %3;" : "=l"(d) : "l"(a), "l"(b), "l"(c));
    return d;
}
__device__ __forceinline__ u64 f2add(u64 a, u64 b) {
    u64 d;
    asm("add.rn.f32x2 %0, %1, %2;" : "=l"(d) : "l"(a), "l"(b));
    return d;
}
__device__ __forceinline__ u64 f2pack(float lo, float hi) {
    u64 v;
    asm("mov.b64 %0, {%1, %2};" : "=l"(v) : "f"(lo), "f"(hi));
    return v;
}
__device__ __forceinline__ void f2unpack(u64 v, float& lo, float& hi) {
    asm("mov.b64 {%0, %1}, %2;" : "=f"(lo), "=f"(hi) : "l"(v));
}
// ReLU: unpack (free reg-pair split) + 2x FMNMX on the ALU pipe + repack.
// Keeps the fma pipe free for FFMA2.
__device__ __forceinline__ u64 f2relu(u64 v) {
    float lo, hi;
    f2unpack(v, lo, hi);
    lo = fmaxf(lo, 0.0f);
    hi = fmaxf(hi, 0.0f);
    return f2pack(lo, hi);
}

__device__ __forceinline__ u64 dupf(float w) {
    unsigned u = __float_as_uint(w);
    return ((u64)u << 32) | (u64)u;
}

// ---- one dense layer (out[j] = b[j] + sum_k in[k] * W[j][k]) ----------------

template <int L>
__device__ __forceinline__ void dense(const u64* __restrict__ sh,
                                      const u64* __restrict__ in,
                                      u64* __restrict__ out) {
    constexpr int DI = DINf(L);
    constexpr int DO = DOUTf(L);
    const u64* w = sh + WOFF(L);
    const u64* b = sh + BOFF(L);
#pragma unroll
    for (int j = 0; j < DO; j++) {
        u64 acc = b[j];
#pragma unroll
        for (int k = 0; k < DI; k++) {
            acc = f2fma(in[k], w[j * DI + k], acc);
        }
        out[j] = acc;
    }
}

template <int N>
__device__ __forceinline__ void relu_arr(u64* a) {
#pragma unroll
    for (int j = 0; j < N; j++) a[j] = f2relu(a[j]);
}

template <int N>
__device__ __forceinline__ void addrelu_arr(u64* a, const u64* id) {
#pragma unroll
    for (int j = 0; j < N; j++) a[j] = f2relu(f2add(a[j], id[j]));
}

struct Params {
    const float* w[NL];
    const float* b[NL];
};

// ---------------------------------------------------------------------------

__global__ void __launch_bounds__(128)
csnet14_kernel(const float* __restrict__ x, Params P,
               float* __restrict__ out, int npairs) {
    __shared__ u64 sh[SH_SIZE];

    // Cooperative fill: duplicate every weight/bias into a (w,w) 64-bit pair.
#pragma unroll
    for (int L = 0; L < NL; L++) {
        const float* W = P.w[L];
        for (int i = threadIdx.x; i < DINf(L) * DOUTf(L); i += 128)
            sh[WOFF(L) + i] = dupf(W[i]);
        const float* B = P.b[L];
        for (int i = threadIdx.x; i < DOUTf(L); i += 128)
            sh[BOFF(L) + i] = dupf(B[i]);
    }
    __syncthreads();

    int p = blockIdx.x * 128 + threadIdx.x;
    if (p >= npairs) return;

    // Load 2 rows (24 contiguous floats) with 6 vectorized loads.
    const float4* xp = (const float4*)(x + (size_t)p * 24);
    float4 a0 = xp[0], a1 = xp[1], a2 = xp[2];   // row r0
    float4 b0 = xp[3], b1 = xp[4], b2 = xp[5];   // row r1

    u64 h0[12];
    h0[0]  = f2pack(a0.x, b0.x);
    h0[1]  = f2pack(a0.y, b0.y);
    h0[2]  = f2pack(a0.z, b0.z);
    h0[3]  = f2pack(a0.w, b0.w);
    h0[4]  = f2pack(a1.x, b1.x);
    h0[5]  = f2pack(a1.y, b1.y);
    h0[6]  = f2pack(a1.z, b1.z);
    h0[7]  = f2pack(a1.w, b1.w);
    h0[8]  = f2pack(a2.x, b2.x);
    h0[9]  = f2pack(a2.y, b2.y);
    h0[10] = f2pack(a2.z, b2.z);
    h0[11] = f2pack(a2.w, b2.w);

    // Encoder: fc1..fc6, saving skip identities.
    u64 s1[12], s2[11], s3[10], s4[9], s5[8], s6[7];
    dense<0>(sh, h0, s1); relu_arr<12>(s1);
    dense<1>(sh, s1, s2); relu_arr<11>(s2);
    dense<2>(sh, s2, s3); relu_arr<10>(s3);
    dense<3>(sh, s3, s4); relu_arr<9>(s4);
    dense<4>(sh, s4, s5); relu_arr<8>(s5);
    dense<5>(sh, s5, s6); relu_arr<7>(s6);

    // Bottleneck fc7.
    u64 t7[6];
    dense<6>(sh, s6, t7); relu_arr<6>(t7);

    // Decoder fc8..fc13: add matching identity before ReLU.
    u64 t8[7], t9[8], t10[9], t11[10], t12[11], t13[12];
    dense<7>(sh, t7, t8);   addrelu_arr<7>(t8, s6);
    dense<8>(sh, t8, t9);   addrelu_arr<8>(t9, s5);
    dense<9>(sh, t9, t10);  addrelu_arr<9>(t10, s4);
    dense<10>(sh, t10, t11); addrelu_arr<10>(t11, s3);
    dense<11>(sh, t11, t12); addrelu_arr<11>(t12, s2);
    dense<12>(sh, t12, t13); addrelu_arr<12>(t13, s1);

    // fc14 -> 2 logits per row.
    u64 z[2];
    dense<13>(sh, t13, z);

    float z00, z01, z10, z11;
    f2unpack(z[0], z00, z01);  // class 0 logits for rows r0, r1
    f2unpack(z[1], z10, z11);  // class 1 logits for rows r0, r1

    float4 o;
    {
        float m = fmaxf(z00, z10);
        float e0 = __expf(z00 - m), e1 = __expf(z10 - m);
        float inv = 1.0f / (e0 + e1);
        o.x = e0 * inv;
        o.y = e1 * inv;
    }
    {
        float m = fmaxf(z01, z11);
        float e0 = __expf(z01 - m), e1 = __expf(z11 - m);
        float inv = 1.0f / (e0 + e1);
        o.z = e0 * inv;
        o.w = e1 * inv;
    }
    ((float4*)out)[p] = o;
}

// ---------------------------------------------------------------------------

extern "C" void kernel_launch(void* const* d_in, const int* in_sizes, int n_in,
                              void* d_out, int out_size) {
    const float* x = (const float*)d_in[0];
    Params P;
    for (int i = 0; i < NL; i++) {
        P.w[i] = (const float*)d_in[1 + 2 * i];
        P.b[i] = (const float*)d_in[2 + 2 * i];
    }
    int nrows = in_sizes[0] / 12;
    int npairs = nrows / 2;   // BATCH is even (2,000,000)
    int grid = (npairs + 127) / 128;
    csnet14_kernel<<<grid, 128>>>(x, P, (float*)d_out, npairs);
}

// round 7
// speedup vs baseline: 1.4087x; 1.4087x over previous
#include <cuda_runtime.h>

// ---------------------------------------------------------------------------
// CSNet14 R6: row-pair f32x2 FFMA2 kernel.
//   - weights duplicated as (w,w) u64 pairs in SMEM, rows padded to even
//     length + 16B aligned so the inner loop uses LDS.128 (ulonglong2):
//     halves shared-load instruction count vs R3.
//   - ReLU via unpack + 2x FMNMX + pack (max.f32x2 rejected by this ptxas).
//   - __launch_bounds__(128,3) caps regs at 168 -> 3 CTAs (12 warps)/SM.
// ---------------------------------------------------------------------------

typedef unsigned long long u64;

#define NL 14

__host__ __device__ constexpr int DINf(int l) {
    const int d[NL] = {12, 12, 11, 10, 9, 8, 7, 6, 7, 8, 9, 10, 11, 12};
    return d[l];
}
__host__ __device__ constexpr int DOUTf(int l) {
    const int d[NL] = {12, 11, 10, 9, 8, 7, 6, 7, 8, 9, 10, 11, 12, 2};
    return d[l];
}
// padded (even) input dim -> every weight row starts 16B-aligned in u64 space
__host__ __device__ constexpr int DIPf(int l) { return (DINf(l) + 1) & ~1; }

__host__ __device__ constexpr int WPOFF(int l) {
    int s = 0;
    for (int i = 0; i < l; i++) s += DIPf(i) * DOUTf(i);
    return s;
}
__host__ __device__ constexpr int BOFF(int l) {
    int s = WPOFF(NL);
    for (int i = 0; i < l; i++) s += DOUTf(i);
    return s;
}
#define SH_SIZE (BOFF(NL))   // 1226 weights(padded) + 122 biases = 1348 u64

// ---- packed f32x2 primitives ------------------------------------------------

__device__ __forceinline__ u64 f2fma(u64 a, u64 b, u64 c) {
    u64 d;
    asm("fma.rn.f32x2 %0, %1, %2, %3;" : "=l"(d) : "l"(a), "l"(b), "l"(c));
    return d;
}
__device__ __forceinline__ u64 f2add(u64 a, u64 b) {
    u64 d;
    asm("add.rn.f32x2 %0, %1, %2;" : "=l"(d) : "l"(a), "l"(b));
    return d;
}
__device__ __forceinline__ u64 f2pack(float lo, float hi) {
    u64 v;
    asm("mov.b64 %0, {%1, %2};" : "=l"(v) : "f"(lo), "f"(hi));
    return v;
}
__device__ __forceinline__ void f2unpack(u64 v, float& lo, float& hi) {
    asm("mov.b64 {%0, %1}, %2;" : "=f"(lo), "=f"(hi) : "l"(v));
}
// ReLU: unpack (reg-pair aliasing, usually free) + 2x FMNMX (alu pipe) + pack.
__device__ __forceinline__ u64 f2relu(u64 v) {
    float lo, hi;
    f2unpack(v, lo, hi);
    lo = fmaxf(lo, 0.0f);
    hi = fmaxf(hi, 0.0f);
    return f2pack(lo, hi);
}
__device__ __forceinline__ u64 dupf(float w) {
    unsigned u = __float_as_uint(w);
    return ((u64)u << 32) | (u64)u;
}

// ---- one dense layer: out[j] = b[j] + sum_k in[k]*W[j][k], LDS.128 weights --

template <int L>
__device__ __forceinline__ void dense(const u64* __restrict__ sh,
                                      const u64* __restrict__ in,
                                      u64* __restrict__ out) {
    constexpr int DI  = DINf(L);
    constexpr int DIp = DIPf(L);
    constexpr int DO  = DOUTf(L);
    constexpr int NP  = DI / 2;           // full (w,w),(w,w) 16B pairs per row
    const u64* b = sh + BOFF(L);
#pragma unroll
    for (int j = 0; j < DO; j++) {
        const ulonglong2* wr =
            reinterpret_cast<const ulonglong2*>(sh + WPOFF(L) + j * DIp);
        u64 acc = b[j];
#pragma unroll
        for (int i = 0; i < NP; i++) {
            ulonglong2 w2 = wr[i];        // LDS.128 broadcast: 2 weights
            acc = f2fma(in[2 * i],     w2.x, acc);
            acc = f2fma(in[2 * i + 1], w2.y, acc);
        }
        if (DI & 1) {                     // odd tail, scalar LDS.64
            acc = f2fma(in[DI - 1], sh[WPOFF(L) + j * DIp + DI - 1], acc);
        }
        out[j] = acc;
    }
}

template <int N>
__device__ __forceinline__ void relu_arr(u64* a) {
#pragma unroll
    for (int j = 0; j < N; j++) a[j] = f2relu(a[j]);
}

template <int N>
__device__ __forceinline__ void addrelu_arr(u64* a, const u64* id) {
#pragma unroll
    for (int j = 0; j < N; j++) a[j] = f2relu(f2add(a[j], id[j]));
}

struct Params {
    const float* w[NL];
    const float* b[NL];
};

// ---------------------------------------------------------------------------

__global__ void __launch_bounds__(128, 3)
csnet14_kernel(const float* __restrict__ x, Params P,
               float* __restrict__ out, int npairs) {
    __shared__ alignas(16) u64 sh[SH_SIZE];

    // Cooperative fill: duplicate every weight into a (w,w) pair; padded
    // slots (k >= DI) get zero.
#pragma unroll
    for (int L = 0; L < NL; L++) {
        const float* W = P.w[L];
        const int di = DINf(L), dip = DIPf(L), dof = DOUTf(L);
        for (int i = threadIdx.x; i < dip * dof; i += 128) {
            int j = i / dip, k = i % dip;
            sh[WPOFF(L) + i] = (k < di) ? dupf(W[j * di + k]) : 0ULL;
        }
        const float* B = P.b[L];
        for (int i = threadIdx.x; i < dof; i += 128)
            sh[BOFF(L) + i] = dupf(B[i]);
    }
    __syncthreads();

    int p = blockIdx.x * 128 + threadIdx.x;
    if (p >= npairs) return;

    // Load 2 rows (24 contiguous floats) with 6 vectorized loads.
    const float4* xp = (const float4*)(x + (size_t)p * 24);
    float4 a0 = xp[0], a1 = xp[1], a2 = xp[2];   // row r0
    float4 b0 = xp[3], b1 = xp[4], b2 = xp[5];   // row r1

    u64 h0[12];
    h0[0]  = f2pack(a0.x, b0.x);
    h0[1]  = f2pack(a0.y, b0.y);
    h0[2]  = f2pack(a0.z, b0.z);
    h0[3]  = f2pack(a0.w, b0.w);
    h0[4]  = f2pack(a1.x, b1.x);
    h0[5]  = f2pack(a1.y, b1.y);
    h0[6]  = f2pack(a1.z, b1.z);
    h0[7]  = f2pack(a1.w, b1.w);
    h0[8]  = f2pack(a2.x, b2.x);
    h0[9]  = f2pack(a2.y, b2.y);
    h0[10] = f2pack(a2.z, b2.z);
    h0[11] = f2pack(a2.w, b2.w);

    // Encoder: fc1..fc6, saving skip identities.
    u64 s1[12], s2[11], s3[10], s4[9], s5[8], s6[7];
    dense<0>(sh, h0, s1); relu_arr<12>(s1);
    dense<1>(sh, s1, s2); relu_arr<11>(s2);
    dense<2>(sh, s2, s3); relu_arr<10>(s3);
    dense<3>(sh, s3, s4); relu_arr<9>(s4);
    dense<4>(sh, s4, s5); relu_arr<8>(s5);
    dense<5>(sh, s5, s6); relu_arr<7>(s6);

    // Bottleneck fc7.
    u64 t7[6];
    dense<6>(sh, s6, t7); relu_arr<6>(t7);

    // Decoder fc8..fc13: add matching identity before ReLU.
    u64 t8[7], t9[8], t10[9], t11[10], t12[11], t13[12];
    dense<7>(sh, t7, t8);    addrelu_arr<7>(t8, s6);
    dense<8>(sh, t8, t9);    addrelu_arr<8>(t9, s5);
    dense<9>(sh, t9, t10);   addrelu_arr<9>(t10, s4);
    dense<10>(sh, t10, t11); addrelu_arr<10>(t11, s3);
    dense<11>(sh, t11, t12); addrelu_arr<11>(t12, s2);
    dense<12>(sh, t12, t13); addrelu_arr<12>(t13, s1);

    // fc14 -> 2 logits per row.
    u64 z[2];
    dense<13>(sh, t13, z);

    float z00, z01, z10, z11;
    f2unpack(z[0], z00, z01);  // class-0 logits for rows r0, r1
    f2unpack(z[1], z10, z11);  // class-1 logits for rows r0, r1

    float4 o;
    {
        float m = fmaxf(z00, z10);
        float e0 = __expf(z00 - m), e1 = __expf(z10 - m);
        float inv = 1.0f / (e0 + e1);
        o.x = e0 * inv;
        o.y = e1 * inv;
    }
    {
        float m = fmaxf(z01, z11);
        float e0 = __expf(z01 - m), e1 = __expf(z11 - m);
        float inv = 1.0f / (e0 + e1);
        o.z = e0 * inv;
        o.w = e1 * inv;
    }
    ((float4*)out)[p] = o;
}

// ---------------------------------------------------------------------------

extern "C" void kernel_launch(void* const* d_in, const int* in_sizes, int n_in,
                              void* d_out, int out_size) {
    const float* x = (const float*)d_in[0];
    Params P;
    for (int i = 0; i < NL; i++) {
        P.w[i] = (const float*)d_in[1 + 2 * i];
        P.b[i] = (const float*)d_in[2 + 2 * i];
    }
    int nrows = in_sizes[0] / 12;
    int npairs = nrows / 2;   // BATCH is even (2,000,000)
    int grid = (npairs + 127) / 128;
    csnet14_kernel<<<grid, 128>>>(x, P, (float*)d_out, npairs);
}